// round 4
// baseline (speedup 1.0000x reference)
#include <cuda_runtime.h>
#include <cuda_bf16.h>

#define N_NODES 8192
#define F_IN    256
#define F_OUT   128
#define CAP     1024   // max neighbors per row stored in shared (mean ~82, P(>1024) ~ 0)

// Scratch (no cudaMalloc allowed): x' [N,F_OUT], s_src[N], s_dst[N]
__device__ float g_xprime[N_NODES * F_OUT];
__device__ float g_ssrc[N_NODES];
__device__ float g_sdst[N_NODES];

// ---------------------------------------------------------------------------
// K1: x' = input @ weight + bias, plus fused s_src = x'·phi_src, s_dst = x'·phi_dst
// Block: 256 threads = 32 (tx: 4 cols each -> 128 cols) x 8 (ty: 8 rows each -> 64 rows)
// ---------------------------------------------------------------------------
__global__ __launch_bounds__(256) void gemm_score_kernel(
    const float* __restrict__ input,    // [N, F_IN]
    const float* __restrict__ weight,   // [F_IN, F_OUT]
    const float* __restrict__ bias,     // [F_OUT]
    const float* __restrict__ phi)      // [2*F_OUT]
{
    __shared__ float inpT[32][68];      // [kk][row], padded (68) to dodge conflicts
    __shared__ float wsh[32][128];      // [kk][f]

    const int tx = threadIdx.x & 31;
    const int ty = threadIdx.x >> 5;
    const int r0 = blockIdx.x * 64;

    float acc[8][4];
    #pragma unroll
    for (int r = 0; r < 8; r++)
        #pragma unroll
        for (int c = 0; c < 4; c++) acc[r][c] = 0.f;

    for (int k0 = 0; k0 < F_IN; k0 += 32) {
        // Fill input chunk transposed: inpT[kk][r] = input[r0+r][k0+kk]
        #pragma unroll
        for (int i = 0; i < 8; i++) {
            int e  = threadIdx.x + i * 256;   // 0..2047
            int r  = e >> 5;
            int kk = e & 31;
            inpT[kk][r] = input[(size_t)(r0 + r) * F_IN + k0 + kk];
        }
        // Fill weight chunk: wsh[kk][f] = weight[k0+kk][f]
        #pragma unroll
        for (int i = 0; i < 16; i++) {
            int e  = threadIdx.x + i * 256;   // 0..4095
            int kk = e >> 7;
            int f  = e & 127;
            wsh[kk][f] = weight[(size_t)(k0 + kk) * F_OUT + f];
        }
        __syncthreads();

        #pragma unroll
        for (int kk = 0; kk < 32; kk++) {
            float4 b  = *(const float4*)&wsh[kk][tx * 4];
            float4 a0 = *(const float4*)&inpT[kk][ty * 8];
            float4 a1 = *(const float4*)&inpT[kk][ty * 8 + 4];
            float av[8] = {a0.x, a0.y, a0.z, a0.w, a1.x, a1.y, a1.z, a1.w};
            #pragma unroll
            for (int r = 0; r < 8; r++) {
                acc[r][0] = fmaf(av[r], b.x, acc[r][0]);
                acc[r][1] = fmaf(av[r], b.y, acc[r][1]);
                acc[r][2] = fmaf(av[r], b.z, acc[r][2]);
                acc[r][3] = fmaf(av[r], b.w, acc[r][3]);
            }
        }
        __syncthreads();
    }

    // Epilogue: add bias, write x', fused score dots (warp = full feature range)
    float4 bi = *(const float4*)&bias[tx * 4];
    float4 ps = *(const float4*)&phi[tx * 4];           // phi_src
    float4 pd = *(const float4*)&phi[F_OUT + tx * 4];   // phi_dst

    #pragma unroll
    for (int r = 0; r < 8; r++) {
        float4 v;
        v.x = acc[r][0] + bi.x;
        v.y = acc[r][1] + bi.y;
        v.z = acc[r][2] + bi.z;
        v.w = acc[r][3] + bi.w;
        int row = r0 + ty * 8 + r;
        *(float4*)&g_xprime[(size_t)row * F_OUT + tx * 4] = v;

        float psum = v.x * ps.x + v.y * ps.y + v.z * ps.z + v.w * ps.w;
        float dsum = v.x * pd.x + v.y * pd.y + v.z * pd.z + v.w * pd.w;
        #pragma unroll
        for (int o = 16; o; o >>= 1) {
            psum += __shfl_xor_sync(0xffffffffu, psum, o);
            dsum += __shfl_xor_sync(0xffffffffu, dsum, o);
        }
        if (tx == 0) {
            g_ssrc[row] = psum;
            g_sdst[row] = dsum;
        }
    }
}

// ---------------------------------------------------------------------------
// K2: per-row sparse masked softmax + aggregation.
// One block (256 threads) per row. exp(-1e9 - m) underflows to 0 in fp32, so
// only adj>0 entries plus the self-loop contribute — exactly matching the ref.
// ---------------------------------------------------------------------------
__global__ __launch_bounds__(256) void attn_kernel(
    const float* __restrict__ adj,      // [N, N]
    float* __restrict__ out)            // [N, F_OUT]
{
    __shared__ int   nb_idx[CAP];
    __shared__ float nb_s[CAP];
    __shared__ float redsh[8];
    __shared__ float hacc[F_OUT];
    __shared__ int   cnt;
    __shared__ float bm, bz;

    const int tid = threadIdx.x;
    const int row = blockIdx.x;

    if (tid == 0) cnt = 0;
    __syncthreads();

    const float si = g_ssrc[row];
    const float4* arow = (const float4*)(adj + (size_t)row * N_NODES);

    // Phase A: scan adjacency row, compact neighbors, track max score
    float lmax = -1e30f;
    #pragma unroll
    for (int i = 0; i < N_NODES / 4 / 256; i++) {
        int k = tid + i * 256;
        float4 a = arow[k];
        int jb = k * 4;
        float comps[4] = {a.x, a.y, a.z, a.w};
        #pragma unroll
        for (int c = 0; c < 4; c++) {
            int j = jb + c;
            if (comps[c] > 0.f || j == row) {
                float S = si + g_sdst[j];
                S = (S >= 0.f) ? S : 0.2f * S;   // leaky relu, slope 0.2
                int p = atomicAdd(&cnt, 1);
                if (p < CAP) { nb_idx[p] = j; nb_s[p] = S; }
                lmax = fmaxf(lmax, S);
            }
        }
    }

    // Block max reduce
    #pragma unroll
    for (int o = 16; o; o >>= 1) lmax = fmaxf(lmax, __shfl_xor_sync(0xffffffffu, lmax, o));
    if ((tid & 31) == 0) redsh[tid >> 5] = lmax;
    __syncthreads();   // also finalizes cnt + nb_* lists
    if (tid < 8) {
        float v = redsh[tid];
        #pragma unroll
        for (int o = 4; o; o >>= 1) v = fmaxf(v, __shfl_xor_sync(0xffu, v, o, 8));
        if (tid == 0) bm = v;
    }
    __syncthreads();
    const float m = bm;
    const int n = (cnt < CAP) ? cnt : CAP;

    // Phase B: exponentiate in place, sum reduce
    float lsum = 0.f;
    for (int p = tid; p < n; p += 256) {
        float e = __expf(nb_s[p] - m);
        nb_s[p] = e;
        lsum += e;
    }
    #pragma unroll
    for (int o = 16; o; o >>= 1) lsum += __shfl_xor_sync(0xffffffffu, lsum, o);
    if ((tid & 31) == 0) redsh[tid >> 5] = lsum;
    __syncthreads();
    if (tid < 8) {
        float v = redsh[tid];
        #pragma unroll
        for (int o = 4; o; o >>= 1) v += __shfl_xor_sync(0xffu, v, o, 8);
        if (tid == 0) bz = v;
    }
    __syncthreads();
    const float rinv = 1.f / bz;

    // Phase C: gather-accumulate h[row][f] = (1/Z) * sum_j e_j * x'[j][f]
    // 2 threads per feature (part 0/1 over interleaved list halves).
    const int f = tid & 127;
    const int part = tid >> 7;
    float acc = 0.f;
    const float* xp = g_xprime + f;
    for (int p = part; p < n; p += 2)
        acc = fmaf(nb_s[p], xp[(size_t)nb_idx[p] * F_OUT], acc);

    if (part == 0) hacc[f] = acc;
    __syncthreads();
    if (part == 1)
        out[(size_t)row * F_OUT + f] = (hacc[f] + acc) * rinv;
}

extern "C" void kernel_launch(void* const* d_in, const int* in_sizes, int n_in,
                              void* d_out, int out_size) {
    const float* adj    = (const float*)d_in[0];
    const float* input  = (const float*)d_in[1];
    const float* weight = (const float*)d_in[2];
    const float* bias   = (const float*)d_in[3];
    const float* phi    = (const float*)d_in[4];
    float* out = (float*)d_out;

    gemm_score_kernel<<<N_NODES / 64, 256>>>(input, weight, bias, phi);
    attn_kernel<<<N_NODES, 256>>>(adj, out);
}

// round 5
// speedup vs baseline: 1.4429x; 1.4429x over previous
#include <cuda_runtime.h>
#include <cuda_bf16.h>

#define N_NODES 8192
#define F_IN    256
#define F_OUT   128
#define CAP     1024   // max neighbors per row (mean ~82, sd ~9; 1024 is >100 sd)

// Scratch (no cudaMalloc allowed): x' [N,F_OUT], s_src[N], s_dst[N]
__device__ float g_xprime[N_NODES * F_OUT];
__device__ float g_ssrc[N_NODES];
__device__ float g_sdst[N_NODES];

// ---------------------------------------------------------------------------
// K1: x' = input @ weight + bias, fused s_src = x'·phi_src, s_dst = x'·phi_dst
// 512 threads: tx (0..31) -> 4 cols each (128 cols), ty (0..15) -> 4 rows (64 rows)
// ---------------------------------------------------------------------------
__global__ __launch_bounds__(512) void gemm_score_kernel(
    const float* __restrict__ input,    // [N, F_IN]
    const float* __restrict__ weight,   // [F_IN, F_OUT]
    const float* __restrict__ bias,     // [F_OUT]
    const float* __restrict__ phi)      // [2*F_OUT]
{
    __shared__ float inpT[32][68];      // [kk][row], padded to dodge conflicts
    __shared__ float wsh[32][128];      // [kk][f]

    const int tx = threadIdx.x & 31;
    const int ty = threadIdx.x >> 5;    // 0..15, constant within a warp
    const int r0 = blockIdx.x * 64;

    float acc[4][4];
    #pragma unroll
    for (int r = 0; r < 4; r++)
        #pragma unroll
        for (int c = 0; c < 4; c++) acc[r][c] = 0.f;

    for (int k0 = 0; k0 < F_IN; k0 += 32) {
        // inpT[kk][r] = input[r0+r][k0+kk]   (2048 elems / 512 thr = 4 each)
        #pragma unroll
        for (int i = 0; i < 4; i++) {
            int e  = threadIdx.x + i * 512;
            int r  = e >> 5;
            int kk = e & 31;
            inpT[kk][r] = input[(size_t)(r0 + r) * F_IN + k0 + kk];
        }
        // wsh[kk][f] = weight[k0+kk][f]      (4096 / 512 = 8 each)
        #pragma unroll
        for (int i = 0; i < 8; i++) {
            int e  = threadIdx.x + i * 512;
            int kk = e >> 7;
            int f  = e & 127;
            wsh[kk][f] = weight[(size_t)(k0 + kk) * F_OUT + f];
        }
        __syncthreads();

        #pragma unroll
        for (int kk = 0; kk < 32; kk++) {
            float4 b = *(const float4*)&wsh[kk][tx * 4];
            float4 a = *(const float4*)&inpT[kk][ty * 4];
            float av[4] = {a.x, a.y, a.z, a.w};
            #pragma unroll
            for (int r = 0; r < 4; r++) {
                acc[r][0] = fmaf(av[r], b.x, acc[r][0]);
                acc[r][1] = fmaf(av[r], b.y, acc[r][1]);
                acc[r][2] = fmaf(av[r], b.z, acc[r][2]);
                acc[r][3] = fmaf(av[r], b.w, acc[r][3]);
            }
        }
        __syncthreads();
    }

    // Epilogue: bias, write x', fused score dots (warp spans full feature range)
    float4 bi = *(const float4*)&bias[tx * 4];
    float4 ps = *(const float4*)&phi[tx * 4];           // phi_src
    float4 pd = *(const float4*)&phi[F_OUT + tx * 4];   // phi_dst

    #pragma unroll
    for (int r = 0; r < 4; r++) {
        float4 v;
        v.x = acc[r][0] + bi.x;
        v.y = acc[r][1] + bi.y;
        v.z = acc[r][2] + bi.z;
        v.w = acc[r][3] + bi.w;
        int row = r0 + ty * 4 + r;
        *(float4*)&g_xprime[(size_t)row * F_OUT + tx * 4] = v;

        float psum = v.x * ps.x + v.y * ps.y + v.z * ps.z + v.w * ps.w;
        float dsum = v.x * pd.x + v.y * pd.y + v.z * pd.z + v.w * pd.w;
        #pragma unroll
        for (int o = 16; o; o >>= 1) {
            psum += __shfl_xor_sync(0xffffffffu, psum, o);
            dsum += __shfl_xor_sync(0xffffffffu, dsum, o);
        }
        if (tx == 0) {
            g_ssrc[row] = psum;
            g_sdst[row] = dsum;
        }
    }
}

// ---------------------------------------------------------------------------
// K2: per-row sparse masked softmax + aggregation. One block (256 thr) per row.
// exp(-1e9 - m) underflows to exactly 0 in fp32, so only adj>0 entries plus
// the self-loop contribute — exactly matching the dense reference.
// ---------------------------------------------------------------------------
__global__ __launch_bounds__(256) void attn_kernel(
    const float* __restrict__ adj,      // [N, N], values are exactly 0.0f or 1.0f
    float* __restrict__ out)            // [N, F_OUT]
{
    __shared__ int   nb_idx[CAP];
    __shared__ float nb_s[CAP];
    __shared__ float hpart[8][F_OUT];   // per-warp gather partials (4 KB)
    __shared__ float redsh[8];
    __shared__ int   cnt;
    __shared__ float bm, bz;

    const int tid  = threadIdx.x;
    const int row  = blockIdx.x;
    const int lane = tid & 31;
    const int wid  = tid >> 5;

    const float si = g_ssrc[row];

    float lmax = -1e30f;
    if (tid == 0) {
        // self-loop entry (mask = adj + I > 0 always includes the diagonal)
        float S = si + g_sdst[row];
        S = (S >= 0.f) ? S : 0.2f * S;
        nb_idx[0] = row;
        nb_s[0]   = S;
        cnt = 1;
        lmax = S;
    }
    __syncthreads();

    // Phase A: stream adjacency row (evict-first), group fast path via bit-OR.
    // adj values are exactly 0.0/1.0, so nonzero bits <=> edge present.
    const uint4* arow = (const uint4*)(adj + (size_t)row * N_NODES);
    #pragma unroll
    for (int i = 0; i < N_NODES / 4 / 256; i++) {
        int k = tid + i * 256;
        uint4 a = __ldcs(arow + k);
        if (a.x | a.y | a.z | a.w) {
            int jb = k * 4;
            unsigned comps[4] = {a.x, a.y, a.z, a.w};
            #pragma unroll
            for (int c = 0; c < 4; c++) {
                int j = jb + c;
                if (comps[c] != 0u && j != row) {   // diagonal handled above
                    float S = si + g_sdst[j];
                    S = (S >= 0.f) ? S : 0.2f * S;  // leaky relu, slope 0.2
                    int p = atomicAdd(&cnt, 1);
                    if (p < CAP) { nb_idx[p] = j; nb_s[p] = S; }
                    lmax = fmaxf(lmax, S);
                }
            }
        }
    }

    // Block max reduce
    #pragma unroll
    for (int o = 16; o; o >>= 1) lmax = fmaxf(lmax, __shfl_xor_sync(0xffffffffu, lmax, o));
    if (lane == 0) redsh[wid] = lmax;
    __syncthreads();   // also finalizes cnt + nb lists
    if (tid < 8) {
        float v = redsh[tid];
        #pragma unroll
        for (int o = 4; o; o >>= 1) v = fmaxf(v, __shfl_xor_sync(0xffu, v, o, 8));
        if (tid == 0) bm = v;
    }
    __syncthreads();
    const float m = bm;
    const int n = (cnt < CAP) ? cnt : CAP;

    // Phase B: exponentiate in place, sum reduce
    float lsum = 0.f;
    for (int p = tid; p < n; p += 256) {
        float e = __expf(nb_s[p] - m);
        nb_s[p] = e;
        lsum += e;
    }
    #pragma unroll
    for (int o = 16; o; o >>= 1) lsum += __shfl_xor_sync(0xffffffffu, lsum, o);
    if (lane == 0) redsh[wid] = lsum;
    __syncthreads();
    if (tid < 8) {
        float v = redsh[tid];
        #pragma unroll
        for (int o = 4; o; o >>= 1) v += __shfl_xor_sync(0xffu, v, o, 8);
        if (tid == 0) bz = v;
    }
    __syncthreads();
    const float rinv = 1.f / bz;

    // Phase C: warp-per-neighbor gather. Each warp loads the full 128-float
    // x' row with float4 (512 B = 1 LDG.128/lane), 8 warps stride the list.
    float4 acc = make_float4(0.f, 0.f, 0.f, 0.f);
    #pragma unroll 4
    for (int p = wid; p < n; p += 8) {
        int   j = nb_idx[p];
        float e = nb_s[p];
        float4 v = *(const float4*)&g_xprime[(size_t)j * F_OUT + lane * 4];
        acc.x = fmaf(e, v.x, acc.x);
        acc.y = fmaf(e, v.y, acc.y);
        acc.z = fmaf(e, v.z, acc.z);
        acc.w = fmaf(e, v.w, acc.w);
    }
    *(float4*)&hpart[wid][lane * 4] = acc;
    __syncthreads();

    if (tid < F_OUT) {
        float s = 0.f;
        #pragma unroll
        for (int w = 0; w < 8; w++) s += hpart[w][tid];
        out[(size_t)row * F_OUT + tid] = s * rinv;
    }
}

extern "C" void kernel_launch(void* const* d_in, const int* in_sizes, int n_in,
                              void* d_out, int out_size) {
    const float* adj    = (const float*)d_in[0];
    const float* input  = (const float*)d_in[1];
    const float* weight = (const float*)d_in[2];
    const float* bias   = (const float*)d_in[3];
    const float* phi    = (const float*)d_in[4];
    float* out = (float*)d_out;

    gemm_score_kernel<<<N_NODES / 64, 512>>>(input, weight, bias, phi);
    attn_kernel<<<N_NODES, 256>>>(adj, out);
}